// round 3
// baseline (speedup 1.0000x reference)
#include <cuda_runtime.h>
#include <cstdint>

// ZGate (qudit diagonal phase): D=4, S=1, INDEX=(0,2,5,8), L=10, B=16.
// omega = i  =>  phase(n) = i^p,  p = (d0+d2+d5+d8) & 3,
// digits at bit shifts 18, 14, 8, 2 of n.
// Input x: [2, N, B] float32 (real plane, imag plane). plane = N*B floats.
// Output layout decided at runtime from out_size (see kernel_launch).

__device__ __forceinline__ void phase_cs(unsigned n, float& c, float& s) {
    const unsigned p = ((n >> 18) + (n >> 14) + (n >> 8) + (n >> 2)) & 3u;
    c = (float)((p == 0u) - (p == 2u));
    s = (float)((p == 1u) - (p == 3u));
}

// Case A: output = real part only, [N, B] float32 (out_size == plane).
__global__ __launch_bounds__(256) void zgate_real_kernel(
    const float4* __restrict__ xre, const float4* __restrict__ xim,
    float4* __restrict__ out, long long total4)
{
    const long long t = (long long)blockIdx.x * blockDim.x + threadIdx.x;
    if (t >= total4) return;
    const unsigned n = (unsigned)(t >> 2);   // 4 float4 per row of B=16
    float c, s; phase_cs(n, c, s);
    const float4 re = xre[t], im = xim[t];
    float4 o;
    o.x = c * re.x - s * im.x;
    o.y = c * re.y - s * im.y;
    o.z = c * re.z - s * im.z;
    o.w = c * re.w - s * im.w;
    out[t] = o;
}

// Case B: output = stacked [2, N, B] float32 (out_size == 2*plane).
__global__ __launch_bounds__(256) void zgate_planar_kernel(
    const float4* __restrict__ xre, const float4* __restrict__ xim,
    float4* __restrict__ outre, float4* __restrict__ outim, long long total4)
{
    const long long t = (long long)blockIdx.x * blockDim.x + threadIdx.x;
    if (t >= total4) return;
    const unsigned n = (unsigned)(t >> 2);
    float c, s; phase_cs(n, c, s);
    const float4 re = xre[t], im = xim[t];
    float4 oR, oI;
    oR.x = c * re.x - s * im.x;  oI.x = s * re.x + c * im.x;
    oR.y = c * re.y - s * im.y;  oI.y = s * re.y + c * im.y;
    oR.z = c * re.z - s * im.z;  oI.z = s * re.z + c * im.z;
    oR.w = c * re.w - s * im.w;  oI.w = s * re.w + c * im.w;
    outre[t] = oR;
    outim[t] = oI;
}

// Fallback: interleaved complex, every float store bounds-checked against
// out_size interpreted as float count (minimum-size interpretation; cannot OOB).
__global__ __launch_bounds__(256) void zgate_safe_kernel(
    const float* __restrict__ x, float* __restrict__ out,
    long long plane, long long out_floats)
{
    const long long e = (long long)blockIdx.x * blockDim.x + threadIdx.x;
    if (e >= plane) return;
    const unsigned n = (unsigned)(e >> 4);
    float c, s; phase_cs(n, c, s);
    const float re = x[e], im = x[plane + e];
    const long long o = 2 * e;
    if (o < out_floats)     out[o]     = c * re - s * im;
    if (o + 1 < out_floats) out[o + 1] = s * re + c * im;
}

extern "C" void kernel_launch(void* const* d_in, const int* in_sizes, int n_in,
                              void* d_out, int out_size) {
    const float* x = (const float*)d_in[0];            // [2, N, B]
    const long long plane = (long long)in_sizes[0] / 2; // N*B floats per plane

    const float4* xre = (const float4*)x;
    const float4* xim = (const float4*)(x + plane);

    const int threads = 256;

    if ((long long)out_size == plane) {
        // Real-part-only float32 output, [N, B].
        const long long total4 = plane / 4;
        const int blocks = (int)((total4 + threads - 1) / threads);
        zgate_real_kernel<<<blocks, threads>>>(xre, xim, (float4*)d_out, total4);
    } else if ((long long)out_size == 2 * plane) {
        // Stacked [2, N, B] float32 output (mirrors input convention).
        float* out = (float*)d_out;
        const long long total4 = plane / 4;
        const int blocks = (int)((total4 + threads - 1) / threads);
        zgate_planar_kernel<<<blocks, threads>>>(
            xre, xim, (float4*)out, (float4*)(out + plane), total4);
    } else {
        // Unknown: crash-proof bounded interleaved writes.
        const int blocks = (int)((plane + threads - 1) / threads);
        zgate_safe_kernel<<<blocks, threads>>>(x, (float*)d_out, plane,
                                               (long long)out_size);
    }
}

// round 6
// speedup vs baseline: 1.3274x; 1.3274x over previous
#include <cuda_runtime.h>
#include <cstdint>

// ZGate (qudit diagonal phase): D=4, S=1, INDEX=(0,2,5,8), L=10, B=16.
// phase(n) = i^p, p = ((n>>18)+(n>>14)+(n>>8)+(n>>2)) & 3.
// Output (verified round 3) = REAL part only, [N, B] float32:
//   Re(phase * (re + i*im)) = c*re - s*im  with (c,s) = i^p.
// Exactly one of c,s is nonzero:
//   p=0 -> +re   p=1 -> -im   p=2 -> -re   p=3 -> +im
// => read ONLY the needed plane: 64 MiB in + 64 MiB out (was 192 MiB).
// p is constant over 4 consecutive rows (bits <2 of n unused) = 256 B,
// so every touched 128 B cache line is fully consumed.

__global__ __launch_bounds__(256) void zgate_select_kernel(
    const float4* __restrict__ xre,   // real plane, plane/4 float4
    const float4* __restrict__ xim,   // imag plane
    float4* __restrict__ out,         // [N, B] float32 as float4
    long long total4)
{
    const long long t = (long long)blockIdx.x * blockDim.x + threadIdx.x;
    if (t >= total4) return;

    const unsigned n = (unsigned)(t >> 2);   // 4 float4 per row (B=16)
    const unsigned p = ((n >> 18) + (n >> 14) + (n >> 8) + (n >> 2)) & 3u;

    // p odd -> imag plane; sign negative for p==1,2.
    const float4* __restrict__ src = (p & 1u) ? xim : xre;
    const float sign = (p == 1u || p == 2u) ? -1.0f : 1.0f;

    const float4 v = src[t];
    float4 o;
    o.x = sign * v.x;
    o.y = sign * v.y;
    o.z = sign * v.z;
    o.w = sign * v.w;
    out[t] = o;
}

// ---- fallbacks for other output layouts (kept from round 2/3, defensive) ----

__device__ __forceinline__ void phase_cs(unsigned n, float& c, float& s) {
    const unsigned p = ((n >> 18) + (n >> 14) + (n >> 8) + (n >> 2)) & 3u;
    c = (float)((p == 0u) - (p == 2u));
    s = (float)((p == 1u) - (p == 3u));
}

__global__ __launch_bounds__(256) void zgate_planar_kernel(
    const float4* __restrict__ xre, const float4* __restrict__ xim,
    float4* __restrict__ outre, float4* __restrict__ outim, long long total4)
{
    const long long t = (long long)blockIdx.x * blockDim.x + threadIdx.x;
    if (t >= total4) return;
    const unsigned n = (unsigned)(t >> 2);
    float c, s; phase_cs(n, c, s);
    const float4 re = xre[t], im = xim[t];
    float4 oR, oI;
    oR.x = c * re.x - s * im.x;  oI.x = s * re.x + c * im.x;
    oR.y = c * re.y - s * im.y;  oI.y = s * re.y + c * im.y;
    oR.z = c * re.z - s * im.z;  oI.z = s * re.z + c * im.z;
    oR.w = c * re.w - s * im.w;  oI.w = s * re.w + c * im.w;
    outre[t] = oR;
    outim[t] = oI;
}

__global__ __launch_bounds__(256) void zgate_safe_kernel(
    const float* __restrict__ x, float* __restrict__ out,
    long long plane, long long out_floats)
{
    const long long e = (long long)blockIdx.x * blockDim.x + threadIdx.x;
    if (e >= plane) return;
    const unsigned n = (unsigned)(e >> 4);
    float c, s; phase_cs(n, c, s);
    const float re = x[e], im = x[plane + e];
    const long long o = 2 * e;
    if (o < out_floats)     out[o]     = c * re - s * im;
    if (o + 1 < out_floats) out[o + 1] = s * re + c * im;
}

extern "C" void kernel_launch(void* const* d_in, const int* in_sizes, int n_in,
                              void* d_out, int out_size) {
    const float* x = (const float*)d_in[0];             // [2, N, B]
    const long long plane = (long long)in_sizes[0] / 2; // N*B floats per plane

    const float4* xre = (const float4*)x;
    const float4* xim = (const float4*)(x + plane);

    const int threads = 256;

    if ((long long)out_size == plane) {
        // Real-part-only output (the verified layout).
        const long long total4 = plane / 4;
        const int blocks = (int)((total4 + threads - 1) / threads);
        zgate_select_kernel<<<blocks, threads>>>(xre, xim, (float4*)d_out, total4);
    } else if ((long long)out_size == 2 * plane) {
        float* out = (float*)d_out;
        const long long total4 = plane / 4;
        const int blocks = (int)((total4 + threads - 1) / threads);
        zgate_planar_kernel<<<blocks, threads>>>(
            xre, xim, (float4*)out, (float4*)(out + plane), total4);
    } else {
        const int blocks = (int)((plane + threads - 1) / threads);
        zgate_safe_kernel<<<blocks, threads>>>(x, (float*)d_out, plane,
                                               (long long)out_size);
    }
}

// round 7
// speedup vs baseline: 1.5823x; 1.1921x over previous
#include <cuda_runtime.h>
#include <cstdint>

// ZGate (qudit diagonal phase): D=4, S=1, INDEX=(0,2,5,8), L=10, B=16.
// phase(n) = i^p, p = ((n>>18)+(n>>14)+(n>>8)+(n>>2)) & 3.
// Output (verified) = REAL part only, [N, B] float32:
//   p=0 -> +re   p=1 -> -im   p=2 -> -re   p=3 -> +im
// Read only the selected plane: 64 MiB in + 64 MiB out.
// This round: 4x float4 per thread (MLP=4), block-strided coalesced.

constexpr int VPT = 4;   // float4 per thread

__global__ __launch_bounds__(256) void zgate_select4_kernel(
    const float4* __restrict__ xre,
    const float4* __restrict__ xim,
    float4* __restrict__ out,
    long long total4)
{
    const long long base = (long long)blockIdx.x * (blockDim.x * VPT) + threadIdx.x;

    long long idx[VPT];
    const float4* __restrict__ src[VPT];
    float sign[VPT];
    float4 v[VPT];

    // Address + plane-select phase (ALU only), then batched loads (MLP=VPT).
#pragma unroll
    for (int k = 0; k < VPT; k++) {
        idx[k] = base + (long long)k * blockDim.x;
        const unsigned n = (unsigned)(idx[k] >> 2);   // 4 float4 per row (B=16)
        const unsigned p = ((n >> 18) + (n >> 14) + (n >> 8) + (n >> 2)) & 3u;
        src[k] = (p & 1u) ? xim : xre;
        sign[k] = (p == 1u || p == 2u) ? -1.0f : 1.0f;
    }
#pragma unroll
    for (int k = 0; k < VPT; k++) {
        if (idx[k] < total4) v[k] = src[k][idx[k]];
    }
#pragma unroll
    for (int k = 0; k < VPT; k++) {
        if (idx[k] < total4) {
            float4 o;
            o.x = sign[k] * v[k].x;
            o.y = sign[k] * v[k].y;
            o.z = sign[k] * v[k].z;
            o.w = sign[k] * v[k].w;
            out[idx[k]] = o;
        }
    }
}

// ---- fallbacks for other output layouts (defensive, unchanged) ----

__device__ __forceinline__ void phase_cs(unsigned n, float& c, float& s) {
    const unsigned p = ((n >> 18) + (n >> 14) + (n >> 8) + (n >> 2)) & 3u;
    c = (float)((p == 0u) - (p == 2u));
    s = (float)((p == 1u) - (p == 3u));
}

__global__ __launch_bounds__(256) void zgate_planar_kernel(
    const float4* __restrict__ xre, const float4* __restrict__ xim,
    float4* __restrict__ outre, float4* __restrict__ outim, long long total4)
{
    const long long t = (long long)blockIdx.x * blockDim.x + threadIdx.x;
    if (t >= total4) return;
    const unsigned n = (unsigned)(t >> 2);
    float c, s; phase_cs(n, c, s);
    const float4 re = xre[t], im = xim[t];
    float4 oR, oI;
    oR.x = c * re.x - s * im.x;  oI.x = s * re.x + c * im.x;
    oR.y = c * re.y - s * im.y;  oI.y = s * re.y + c * im.y;
    oR.z = c * re.z - s * im.z;  oI.z = s * re.z + c * im.z;
    oR.w = c * re.w - s * im.w;  oI.w = s * re.w + c * im.w;
    outre[t] = oR;
    outim[t] = oI;
}

__global__ __launch_bounds__(256) void zgate_safe_kernel(
    const float* __restrict__ x, float* __restrict__ out,
    long long plane, long long out_floats)
{
    const long long e = (long long)blockIdx.x * blockDim.x + threadIdx.x;
    if (e >= plane) return;
    const unsigned n = (unsigned)(e >> 4);
    float c, s; phase_cs(n, c, s);
    const float re = x[e], im = x[plane + e];
    const long long o = 2 * e;
    if (o < out_floats)     out[o]     = c * re - s * im;
    if (o + 1 < out_floats) out[o + 1] = s * re + c * im;
}

extern "C" void kernel_launch(void* const* d_in, const int* in_sizes, int n_in,
                              void* d_out, int out_size) {
    const float* x = (const float*)d_in[0];             // [2, N, B]
    const long long plane = (long long)in_sizes[0] / 2; // N*B floats per plane

    const float4* xre = (const float4*)x;
    const float4* xim = (const float4*)(x + plane);

    const int threads = 256;

    if ((long long)out_size == plane) {
        const long long total4 = plane / 4;
        const long long per_block = (long long)threads * VPT;
        const int blocks = (int)((total4 + per_block - 1) / per_block);
        zgate_select4_kernel<<<blocks, threads>>>(xre, xim, (float4*)d_out, total4);
    } else if ((long long)out_size == 2 * plane) {
        float* out = (float*)d_out;
        const long long total4 = plane / 4;
        const int blocks = (int)((total4 + threads - 1) / threads);
        zgate_planar_kernel<<<blocks, threads>>>(
            xre, xim, (float4*)out, (float4*)(out + plane), total4);
    } else {
        const int blocks = (int)((plane + threads - 1) / threads);
        zgate_safe_kernel<<<blocks, threads>>>(x, (float*)d_out, plane,
                                               (long long)out_size);
    }
}